// round 16
// baseline (speedup 1.0000x reference)
#include <cuda_runtime.h>
#include <cuda_bf16.h>
#include <math.h>

#define SEQ 512
#define BATCH 16
#define HID 256
#define VOC 10000
#define VOCP 10240
#define SB (SEQ*BATCH)

// fused-kernel block layout
#define NB_RNN  64
#define NB_WGEN 1024
#define NB_WCVT 1280
#define NB_UB   20
#define NB_ALL  (NB_RNN + NB_WGEN + NB_WCVT + NB_UB)   // 2388 (even)

// ------------------- scratch (device globals; no allocs allowed) ------------
static __device__ float g_X[2][SB*HID];          // pre-activations f/b (bias included)
static __device__ float g_outf[SB*HID];          // forward RNN outputs (tf32) [S][B][H]
static __device__ float g_owf[SB*HID];           // decay-weighted forward (tf32) [S][B][H]
static __device__ __nv_bfloat16 g_ctxh[SB*HID];  // attention context (bf16) [S*B][H]
static __device__ float g_scores[BATCH*SEQ*SEQ]; // w matrix, then scores/alpha [B][S][S]
static __device__ float g_sinv[SB];              // 1/sum_w per (i,b)
static __device__ float g_ub[BATCH*VOC];         // user bias + fc_b  [B][V]
static __device__ __nv_bfloat16 g_Whalf[(size_t)VOCP*HID]; // fcW[:,0:256] bf16 padded
static __device__ float g_hfin[2*BATCH*HID];     // final hidden states [dir][B][H]

// --------------- helpers -----------------------------------------------------
__device__ __forceinline__ unsigned smem_u32(const void* p){
    unsigned a;
    asm("{ .reg .u64 t; cvta.to.shared.u64 t, %1; cvt.u32.u64 %0, t; }"
        : "=r"(a) : "l"(p));
    return a;
}
__device__ __forceinline__ unsigned cluster_rank(){
    unsigned r; asm("mov.u32 %0, %%cluster_ctarank;" : "=r"(r)); return r;
}
__device__ __forceinline__ unsigned mapa_sh(unsigned addr, unsigned rank){
    unsigned r; asm("mapa.shared::cluster.u32 %0, %1, %2;" : "=r"(r) : "r"(addr), "r"(rank));
    return r;
}
__device__ __forceinline__ float to_tf32(float x){
    float r; asm("cvt.rna.tf32.f32 %0, %1;" : "=f"(r) : "f"(x)); return r;
}
__device__ __forceinline__ unsigned bf16x2(float hi, float lo){
    unsigned r; asm("cvt.rn.bf16x2.f32 %0, %1, %2;" : "=r"(r) : "f"(hi), "f"(lo)); return r;
}
__device__ __forceinline__ void mma_tf32(float* acc,
        unsigned a0, unsigned a1, unsigned a2, unsigned a3,
        unsigned b0, unsigned b1){
    asm volatile("mma.sync.aligned.m16n8k8.row.col.f32.tf32.tf32.f32 "
        "{%0,%1,%2,%3}, {%4,%5,%6,%7}, {%8,%9}, {%0,%1,%2,%3};"
        : "+f"(acc[0]), "+f"(acc[1]), "+f"(acc[2]), "+f"(acc[3])
        : "r"(a0), "r"(a1), "r"(a2), "r"(a3), "r"(b0), "r"(b1));
}
__device__ __forceinline__ void mma_bf16(float* acc,
        unsigned a0, unsigned a1, unsigned a2, unsigned a3,
        unsigned b0, unsigned b1){
    asm volatile("mma.sync.aligned.m16n8k16.row.col.f32.bf16.bf16.f32 "
        "{%0,%1,%2,%3}, {%4,%5,%6,%7}, {%8,%9}, {%0,%1,%2,%3};"
        : "+f"(acc[0]), "+f"(acc[1]), "+f"(acc[2]), "+f"(acc[3])
        : "r"(a0), "r"(a1), "r"(a2), "r"(a3), "r"(b0), "r"(b1));
}
__device__ __forceinline__ void cp16(unsigned dst, const void* src){
    asm volatile("cp.async.cg.shared.global [%0], [%1], 16;" :: "r"(dst), "l"(src));
}
__device__ __forceinline__ void st_async_f32(unsigned dst, float v, unsigned mbar){
    asm volatile("st.async.shared::cluster.mbarrier::complete_tx::bytes.b32 [%0], %1, [%2];"
                 :: "r"(dst), "r"(__float_as_uint(v)), "r"(mbar) : "memory");
}
__device__ __forceinline__ void mbar_init(unsigned mbar, unsigned cnt){
    asm volatile("mbarrier.init.shared.b64 [%0], %1;" :: "r"(mbar), "r"(cnt) : "memory");
}
__device__ __forceinline__ void mbar_expect_tx(unsigned mbar, unsigned tx){
    asm volatile("mbarrier.arrive.expect_tx.shared.b64 _, [%0], %1;" :: "r"(mbar), "r"(tx) : "memory");
}
__device__ __forceinline__ void mbar_wait_cluster(unsigned mbar, unsigned parity){
    unsigned done;
    asm volatile(
        "{\n\t.reg .pred p;\n\t"
        "mbarrier.try_wait.parity.acquire.cluster.shared::cta.b64 p, [%1], %2;\n\t"
        "selp.b32 %0, 1, 0, p;\n\t}"
        : "=r"(done) : "r"(mbar), "r"(parity) : "memory");
    if (!done){
        asm volatile(
            "{\n\t.reg .pred P1;\n\t"
            "WL_%=:\n\t"
            "mbarrier.try_wait.parity.acquire.cluster.shared::cta.b64 P1, [%0], %1, 0x989680;\n\t"
            "@P1 bra.uni WD_%=;\n\t"
            "bra.uni WL_%=;\n\t"
            "WD_%=:\n\t}"
            :: "r"(mbar), "r"(parity) : "memory");
    }
}

// packed-f32x2 dot over one 64-col chunk with bank-derotated layout
#define RNN_DOT(RES) do{                                                        \
    unsigned long long acc0 = 0ull, acc1 = 0ull;                                \
    _Pragma("unroll")                                                           \
    for (int j = 0; j < 16; j++){                                               \
        int src = (4*j + 8*q) & 63;                                             \
        float4 h4 = *(const float4*)(hbp + src);                                \
        unsigned long long hp0, hp1;                                            \
        asm("mov.b64 %0, {%1,%2};" : "=l"(hp0) : "f"(h4.x), "f"(h4.y));         \
        asm("mov.b64 %0, {%1,%2};" : "=l"(hp1) : "f"(h4.z), "f"(h4.w));         \
        asm("fma.rn.f32x2 %0, %1, %2, %0;" : "+l"(acc0) : "l"(w2[2*j  ]), "l"(hp0)); \
        asm("fma.rn.f32x2 %0, %1, %2, %0;" : "+l"(acc1) : "l"(w2[2*j+1]), "l"(hp1)); \
    }                                                                           \
    float r0,r1,r2,r3;                                                          \
    asm("mov.b64 {%0,%1}, %2;" : "=f"(r0), "=f"(r1) : "l"(acc0));               \
    asm("mov.b64 {%0,%1}, %2;" : "=f"(r2), "=f"(r3) : "l"(acc1));               \
    RES = (r0+r1) + (r2+r3);                                                    \
} while(0)

// ---- kernel 1 (tf32 MMA): X[dir][m][:] = emb[x[m]] @ Wih^T + bias -----------
__global__ __launch_bounds__(256) void k_xpre_mma(const int* __restrict__ x,
        const float* __restrict__ emb,
        const float* __restrict__ Wf, const float* __restrict__ bf,
        const float* __restrict__ Wb, const float* __restrict__ bb){
    __shared__ float As[128][36];
    __shared__ float Bs[128][36];
    const int dir = blockIdx.z;
    const float* __restrict__ W  = dir ? Wb : Wf;
    const float* __restrict__ bv = dir ? bb : bf;
    float* __restrict__ out = g_X[dir];
    const int tid = threadIdx.x;
    const int lane = tid & 31, wid = tid >> 5;
    const int wr = wid >> 2, wc = wid & 3;
    const int bm = blockIdx.x * 128, bn = blockIdx.y * 128;
    const int gr = lane >> 2, gc = lane & 3;
    const int lr = tid >> 3, lc = (tid & 7) * 4;
    int tok[4];
    #pragma unroll
    for (int p=0;p<4;p++) tok[p] = x[bm + lr + p*32];
    float acc[4][4][4];
    #pragma unroll
    for (int mi=0;mi<4;mi++)
        #pragma unroll
        for (int ni=0;ni<4;ni++)
            #pragma unroll
            for (int rr=0;rr<4;rr++) acc[mi][ni][rr] = 0.f;
    for (int k0 = 0; k0 < HID; k0 += 32){
        #pragma unroll
        for (int p = 0; p < 4; p++){
            int r = lr + p*32;
            float4 av = *(const float4*)(emb + (size_t)tok[p]*HID + k0 + lc);
            As[r][lc+0] = to_tf32(av.x); As[r][lc+1] = to_tf32(av.y);
            As[r][lc+2] = to_tf32(av.z); As[r][lc+3] = to_tf32(av.w);
            float4 wv = *(const float4*)(W + (size_t)(bn+r)*HID + k0 + lc);
            Bs[r][lc+0] = to_tf32(wv.x); Bs[r][lc+1] = to_tf32(wv.y);
            Bs[r][lc+2] = to_tf32(wv.z); Bs[r][lc+3] = to_tf32(wv.w);
        }
        __syncthreads();
        #pragma unroll
        for (int kk = 0; kk < 32; kk += 8){
            unsigned af[4][4];
            #pragma unroll
            for (int mi=0;mi<4;mi++){
                int row = wr*64 + mi*16 + gr;
                af[mi][0] = __float_as_uint(As[row  ][kk+gc  ]);
                af[mi][1] = __float_as_uint(As[row+8][kk+gc  ]);
                af[mi][2] = __float_as_uint(As[row  ][kk+gc+4]);
                af[mi][3] = __float_as_uint(As[row+8][kk+gc+4]);
            }
            unsigned bfr[4][2];
            #pragma unroll
            for (int ni=0;ni<4;ni++){
                int row = wc*32 + ni*8 + gr;
                bfr[ni][0] = __float_as_uint(Bs[row][kk+gc  ]);
                bfr[ni][1] = __float_as_uint(Bs[row][kk+gc+4]);
            }
            #pragma unroll
            for (int mi=0;mi<4;mi++)
                #pragma unroll
                for (int ni=0;ni<4;ni++)
                    mma_tf32(acc[mi][ni], af[mi][0],af[mi][1],af[mi][2],af[mi][3],
                             bfr[ni][0], bfr[ni][1]);
        }
        __syncthreads();
    }
    #pragma unroll
    for (int mi=0;mi<4;mi++){
        int m0 = bm + wr*64 + mi*16 + gr;
        int m1 = m0 + 8;
        #pragma unroll
        for (int ni=0;ni<4;ni++){
            int n0 = bn + wc*32 + ni*8 + gc*2;
            out[(size_t)m0*HID + n0  ] = acc[mi][ni][0] + bv[n0];
            out[(size_t)m0*HID + n0+1] = acc[mi][ni][1] + bv[n0+1];
            out[(size_t)m1*HID + n0  ] = acc[mi][ni][2] + bv[n0];
            out[(size_t)m1*HID + n0+1] = acc[mi][ni][3] + bv[n0+1];
        }
    }
}

// ======== fused kernel: RNN scan (blocks 0..63) + wgen/wcvt/ub helpers =======
__global__ __launch_bounds__(512, 1) __cluster_dims__(2, 1, 1)
void k_fused(const float* __restrict__ Whhf, const float* __restrict__ Whhb,
             const float* __restrict__ h0,
             const float* __restrict__ t_in, const float* __restrict__ s_in,
             const float* __restrict__ fcW,  const float* __restrict__ fcb,
             const int* __restrict__ au,     const float* __restrict__ uemb){
    const int bid = blockIdx.x;
    const int tid = threadIdx.x;

    if (bid < NB_RNN){
        // -------- RNN scan: quad mapping + f32x2 FMA + single barrier -------
        __shared__ float hbuf[2][HID];
        __shared__ __align__(8) unsigned long long mbar[2];
        const unsigned rank = cluster_rank();
        const int cl = bid >> 1;
        const int b = cl & 15, dir = cl >> 4;
        const int row = tid >> 2;     // 0..127
        const int q   = tid & 3;      // 64-col chunk within quad
        const bool own = ((q >> 1) == (int)rank);
        const int grow = (int)rank*128 + row;
        // bank-derotated W slice (chunk j covers cols q*64 + ((4j+8q)&63)..+3)
        const float* Wp = (dir ? Whhb : Whhf) + (size_t)grow*HID + q*64;
        unsigned long long w2[32];
        #pragma unroll
        for (int j = 0; j < 16; j++){
            int src = (4*j + 8*q) & 63;
            float4 wv = *(const float4*)(Wp + src);
            asm("mov.b64 %0, {%1,%2};" : "=l"(w2[2*j  ]) : "f"(wv.x), "f"(wv.y));
            asm("mov.b64 %0, {%1,%2};" : "=l"(w2[2*j+1]) : "f"(wv.z), "f"(wv.w));
        }
        if (tid < HID) hbuf[0][tid] = h0[(size_t)dir*BATCH*HID + b*HID + tid];
        const unsigned hb = smem_u32(&hbuf[0][0]);
        const unsigned mb = smem_u32(&mbar[0]);
        const unsigned hb_peer = mapa_sh(hb, rank^1u);
        const unsigned mb_peer = mapa_sh(mb, rank^1u);
        if (tid == 0){ mbar_init(mb, 1u); mbar_init(mb + 8u, 1u); }
        __syncthreads();
        asm volatile("barrier.cluster.arrive.aligned;" ::: "memory");
        asm volatile("barrier.cluster.wait.aligned;"   ::: "memory");
        const float* __restrict__ Xd = g_X[dir] + (size_t)b*HID + grow;
        float* __restrict__ outp = g_outf + (size_t)b*HID + grow;
        float xv = 0.f;
        if (q == 0){
            int tsrc0 = dir ? (SEQ-1) : 0;
            xv = Xd[(size_t)tsrc0*BATCH*HID];
        }
        for (int t = 0; t < SEQ; t++){
            const int p = t & 1, np = p ^ 1;
            const int tsrc = dir ? (SEQ-1-t) : t;
            if (tid == 0) mbar_expect_tx(mb + (unsigned)np*8u, 512u);
            const float* hbp = &hbuf[p][q*64];
            float part;
            if (own){
                RNN_DOT(part);      // own half: local data, compute immediately
            } else {
                if (t > 0) mbar_wait_cluster(mb + (unsigned)p*8u, (unsigned)(((t-1)>>1)&1));
                RNN_DOT(part);      // peer half after delivery
            }
            part += __shfl_xor_sync(0xffffffffu, part, 1);
            part += __shfl_xor_sync(0xffffffffu, part, 2);
            if (q == 0){
                float hn = tanhf(xv + part);
                hbuf[np][grow] = hn;
                unsigned off = (unsigned)(np*HID + grow)*4u;
                st_async_f32(hb_peer + off, hn, mb_peer + (unsigned)np*8u);
                if (dir == 0) outp[(size_t)tsrc*BATCH*HID] = to_tf32(hn);
                if (t == SEQ-1) g_hfin[(size_t)dir*BATCH*HID + b*HID + grow] = hn;
                if (t + 1 < SEQ){
                    int tn = dir ? (SEQ-2-t) : (t+1);
                    xv = Xd[(size_t)tn*BATCH*HID];
                }
            }
            __syncthreads();
        }
        if (tid == 0) mbar_wait_cluster(mb, 1u);   // drain final delivery
    }
    else if (bid < NB_RNN + NB_WGEN){
        // ---------------- wgen: w matrix (8 query rows) + row sums ----------
        __shared__ float sums[8];
        const int hid = bid - NB_RNN;
        const int i0 = (hid >> 4) * 8, b = hid & 15;
        const float C1 = 6.2831853071795864769e0f / 86400.0f;
        const float C2 = 0.1f / 86400.0f;
        float ti[8], ci[8], sn[8], ei[8]; float2 si[8];
        #pragma unroll
        for (int ii=0;ii<8;ii++){
            ti[ii] = t_in[(i0+ii)*BATCH + b];
            si[ii] = ((const float2*)s_in)[(i0+ii)*BATCH + b];
            ci[ii] = cosf(ti[ii]*C1);
            sn[ii] = sinf(ti[ii]*C1);
            ei[ii] = __expf(-ti[ii]*C2);
        }
        if (tid < 8) sums[tid] = 0.f;
        __syncthreads();
        const int j = tid;   // 512 threads cover SEQ exactly
        float tj = t_in[j*BATCH + b];
        float2 sj = ((const float2*)s_in)[j*BATCH + b];
        float cj = cosf(tj*C1), sjn = sinf(tj*C1), fj = __expf(tj*C2);
        float loc[8];
        #pragma unroll
        for (int ii=0;ii<8;ii++){
            float w = 0.f;
            if (j <= i0+ii){
                float dx = si[ii].x - sj.x, dy = si[ii].y - sj.y;
                float ds = sqrtf(dx*dx + dy*dy);
                float base = (0.5f*(ci[ii]*cj + sn[ii]*sjn) + 0.5f) * (ei[ii]*fj);
                w = base * __expf(-100.0f*ds) + 1e-10f;
            }
            g_scores[((size_t)b*SEQ + i0 + ii)*SEQ + j] = to_tf32(w);
            loc[ii] = w;
        }
        #pragma unroll
        for (int ii=0;ii<8;ii++){
            float v = loc[ii];
            v += __shfl_xor_sync(0xffffffffu, v, 16);
            v += __shfl_xor_sync(0xffffffffu, v, 8);
            v += __shfl_xor_sync(0xffffffffu, v, 4);
            v += __shfl_xor_sync(0xffffffffu, v, 2);
            v += __shfl_xor_sync(0xffffffffu, v, 1);
            if ((tid & 31) == 0) atomicAdd(&sums[ii], v);
        }
        __syncthreads();
        if (tid < 8) g_sinv[(i0+tid)*BATCH + b] = 1.0f / sums[tid];
    }
    else if (bid < NB_RNN + NB_WGEN + NB_WCVT){
        // ---------------- wcvt: fcW[:,0:256] -> bf16, padded ----------------
        size_t idx = ((size_t)(bid - NB_RNN - NB_WGEN))*512 + tid;
        size_t e = idx*4;
        int v = (int)(e >> 8);
        int k = (int)(e & 255);
        float4 w = make_float4(0.f,0.f,0.f,0.f);
        if (v < VOC) w = *(const float4*)(fcW + (size_t)v*768 + k);
        unsigned lo = bf16x2(w.y, w.x);
        unsigned hi = bf16x2(w.w, w.z);
        *(uint2*)(g_Whalf + e) = make_uint2(lo, hi);
    }
    else {
        // ---------------- ub: user bias + fc_b ------------------------------
        __shared__ float ue[BATCH][HID];
        for (int i = tid; i < BATCH*HID; i += 512)
            ue[i >> 8][i & 255] = uemb[(size_t)au[i >> 8]*HID + (i & 255)];
        __syncthreads();
        const int v = (bid - NB_RNN - NB_WGEN - NB_WCVT)*512 + tid;
        if (v < VOC){
            const float* wrow = fcW + (size_t)v*(3*HID) + 2*HID;
            float acc[BATCH];
            #pragma unroll
            for (int r=0;r<BATCH;r++) acc[r]=0.f;
            for (int k=0;k<HID;k+=4){
                float4 w = *(const float4*)(wrow + k);
                #pragma unroll
                for (int r=0;r<BATCH;r++)
                    acc[r] += w.x*ue[r][k] + w.y*ue[r][k+1] + w.z*ue[r][k+2] + w.w*ue[r][k+3];
            }
            float bias = fcb[v];
            #pragma unroll
            for (int r=0;r<BATCH;r++) g_ub[(size_t)r*VOC + v] = acc[r] + bias;
        }
    }
}

// ---- kernel owf_mma: owf[i,b,:] = (w[b,i,:] @ outf[:,b,:]) * sinv[i,b] ------
__global__ __launch_bounds__(256) void k_owf_mma(){
    __shared__ float As[128][36];
    __shared__ float Bs[128][36];
    const int b = blockIdx.z;
    const int bm = blockIdx.x*128;   // i tile
    const int bn = blockIdx.y*128;   // h tile
    const int tid = threadIdx.x;
    const int lane = tid & 31, wid = tid >> 5;
    const int wr = wid >> 2, wc = wid & 3;
    const int gr = lane >> 2, gc = lane & 3;
    float acc[4][4][4];
    #pragma unroll
    for (int mi=0;mi<4;mi++)
        #pragma unroll
        for (int ni=0;ni<4;ni++)
            #pragma unroll
            for (int rr=0;rr<4;rr++) acc[mi][ni][rr] = 0.f;
    const int lr = tid >> 3, lc = (tid & 7) * 4;
    const int bkk = tid >> 3;
    const int bh0 = (tid & 7) * 16;
    const float* Abase = g_scores + (size_t)b*SEQ*SEQ;
    for (int k0 = 0; k0 < SEQ; k0 += 32){
        #pragma unroll
        for (int p = 0; p < 4; p++){
            int r = lr + p*32;
            *(float4*)&As[r][lc] = *(const float4*)(Abase + (size_t)(bm+r)*SEQ + k0 + lc);
        }
        #pragma unroll
        for (int i = 0; i < 4; i++){
            float4 v = *(const float4*)(g_outf + ((size_t)(k0+bkk)*BATCH + b)*HID + bn + bh0 + 4*i);
            Bs[bh0+4*i+0][bkk] = v.x;
            Bs[bh0+4*i+1][bkk] = v.y;
            Bs[bh0+4*i+2][bkk] = v.z;
            Bs[bh0+4*i+3][bkk] = v.w;
        }
        __syncthreads();
        #pragma unroll
        for (int kk = 0; kk < 32; kk += 8){
            unsigned af[4][4];
            #pragma unroll
            for (int mi=0;mi<4;mi++){
                int row = wr*64 + mi*16 + gr;
                af[mi][0] = __float_as_uint(As[row  ][kk+gc  ]);
                af[mi][1] = __float_as_uint(As[row+8][kk+gc  ]);
                af[mi][2] = __float_as_uint(As[row  ][kk+gc+4]);
                af[mi][3] = __float_as_uint(As[row+8][kk+gc+4]);
            }
            unsigned bf[4][2];
            #pragma unroll
            for (int ni=0;ni<4;ni++){
                int row = wc*32 + ni*8 + gr;
                bf[ni][0] = __float_as_uint(Bs[row][kk+gc  ]);
                bf[ni][1] = __float_as_uint(Bs[row][kk+gc+4]);
            }
            #pragma unroll
            for (int mi=0;mi<4;mi++)
                #pragma unroll
                for (int ni=0;ni<4;ni++)
                    mma_tf32(acc[mi][ni], af[mi][0],af[mi][1],af[mi][2],af[mi][3],
                             bf[ni][0], bf[ni][1]);
        }
        __syncthreads();
    }
    #pragma unroll
    for (int mi=0;mi<4;mi++){
        int m0 = bm + wr*64 + mi*16 + gr;
        int m1 = m0 + 8;
        float inv0 = g_sinv[m0*BATCH + b];
        float inv1 = g_sinv[m1*BATCH + b];
        #pragma unroll
        for (int ni=0;ni<4;ni++){
            int n0 = bn + wc*32 + ni*8 + gc*2;
            g_owf[((size_t)m0*BATCH + b)*HID + n0  ] = to_tf32(acc[mi][ni][0]*inv0);
            g_owf[((size_t)m0*BATCH + b)*HID + n0+1] = to_tf32(acc[mi][ni][1]*inv0);
            g_owf[((size_t)m1*BATCH + b)*HID + n0  ] = to_tf32(acc[mi][ni][2]*inv1);
            g_owf[((size_t)m1*BATCH + b)*HID + n0+1] = to_tf32(acc[mi][ni][3]*inv1);
        }
    }
}

// ------- kernel 4a (tf32 MMA): scores[b,q,k] = owf_q . owf_k / sqrt(512) -----
__global__ __launch_bounds__(256) void k_scores_mma(){
    __shared__ float As[128][36];
    __shared__ float Bs[128][36];
    const int b = blockIdx.z;
    const int bm = blockIdx.x*128, bn = blockIdx.y*128;
    const int tid = threadIdx.x;
    const int lane = tid & 31, wid = tid >> 5;
    const int wr = wid >> 2, wc = wid & 3;
    const int gr = lane >> 2, gc = lane & 3;
    float acc[4][4][4];
    #pragma unroll
    for (int mi=0;mi<4;mi++)
        #pragma unroll
        for (int ni=0;ni<4;ni++)
            #pragma unroll
            for (int rr=0;rr<4;rr++) acc[mi][ni][rr] = 0.f;
    const int lr = tid >> 3, lc = (tid & 7) * 4;
    const float* base = g_owf + (size_t)b*HID;
    for (int k0 = 0; k0 < HID; k0 += 32){
        #pragma unroll
        for (int p = 0; p < 4; p++){
            int r = lr + p*32;
            *(float4*)&As[r][lc] = *(const float4*)(base + (size_t)(bm+r)*BATCH*HID + k0 + lc);
            *(float4*)&Bs[r][lc] = *(const float4*)(base + (size_t)(bn+r)*BATCH*HID + k0 + lc);
        }
        __syncthreads();
        #pragma unroll
        for (int kk = 0; kk < 32; kk += 8){
            unsigned af[4][4];
            #pragma unroll
            for (int mi=0;mi<4;mi++){
                int row = wr*64 + mi*16 + gr;
                af[mi][0] = __float_as_uint(As[row  ][kk+gc  ]);
                af[mi][1] = __float_as_uint(As[row+8][kk+gc  ]);
                af[mi][2] = __float_as_uint(As[row  ][kk+gc+4]);
                af[mi][3] = __float_as_uint(As[row+8][kk+gc+4]);
            }
            unsigned bf[4][2];
            #pragma unroll
            for (int ni=0;ni<4;ni++){
                int row = wc*32 + ni*8 + gr;
                bf[ni][0] = __float_as_uint(Bs[row][kk+gc  ]);
                bf[ni][1] = __float_as_uint(Bs[row][kk+gc+4]);
            }
            #pragma unroll
            for (int mi=0;mi<4;mi++)
                #pragma unroll
                for (int ni=0;ni<4;ni++)
                    mma_tf32(acc[mi][ni], af[mi][0],af[mi][1],af[mi][2],af[mi][3],
                             bf[ni][0], bf[ni][1]);
        }
        __syncthreads();
    }
    const float SC = 0.044194173824159220f; // 1/sqrt(512)
    #pragma unroll
    for (int mi=0;mi<4;mi++){
        int m0 = bm + wr*64 + mi*16 + gr;
        int m1 = m0 + 8;
        #pragma unroll
        for (int ni=0;ni<4;ni++){
            int n0 = bn + wc*32 + ni*8 + gc*2;
            g_scores[((size_t)b*SEQ + m0)*SEQ + n0  ] = acc[mi][ni][0]*SC;
            g_scores[((size_t)b*SEQ + m0)*SEQ + n0+1] = acc[mi][ni][1]*SC;
            g_scores[((size_t)b*SEQ + m1)*SEQ + n0  ] = acc[mi][ni][2]*SC;
            g_scores[((size_t)b*SEQ + m1)*SEQ + n0+1] = acc[mi][ni][3]*SC;
        }
    }
}

// ---------------- kernel 4b: softmax rows of 512 (fast exp) ------------------
__global__ __launch_bounds__(256) void k_softmax(){
    const int row = blockIdx.x;
    float* p = g_scores + (size_t)row*SEQ;
    __shared__ float red[256];
    const int tid = threadIdx.x;
    float v0 = p[tid], v1 = p[tid+256];
    red[tid] = fmaxf(v0, v1); __syncthreads();
    for (int off=128; off>0; off>>=1){ if (tid<off) red[tid]=fmaxf(red[tid],red[tid+off]); __syncthreads(); }
    float M = red[0]; __syncthreads();
    float e0 = __expf(v0-M), e1 = __expf(v1-M);
    red[tid] = e0+e1; __syncthreads();
    for (int off=128; off>0; off>>=1){ if (tid<off) red[tid]+=red[tid+off]; __syncthreads(); }
    float inv = 1.0f/red[0];
    p[tid] = to_tf32(e0*inv); p[tid+256] = to_tf32(e1*inv);
}

// ------- kernel 4c (tf32 MMA): ctx = alpha @ owf; stores bf16 ----------------
__global__ __launch_bounds__(256) void k_ctx_mma(){
    __shared__ float As[128][36];
    __shared__ float Bs[128][36];
    const int b = blockIdx.z;
    const int bm = blockIdx.x*128;
    const int bn = blockIdx.y*128;
    const int tid = threadIdx.x;
    const int lane = tid & 31, wid = tid >> 5;
    const int wr = wid >> 2, wc = wid & 3;
    const int gr = lane >> 2, gc = lane & 3;
    float acc[4][4][4];
    #pragma unroll
    for (int mi=0;mi<4;mi++)
        #pragma unroll
        for (int ni=0;ni<4;ni++)
            #pragma unroll
            for (int rr=0;rr<4;rr++) acc[mi][ni][rr] = 0.f;
    const int lr = tid >> 3, lc = (tid & 7) * 4;
    const int bkk = tid >> 3;
    const int bh0 = (tid & 7) * 16;
    const float* Abase = g_scores + (size_t)b*SEQ*SEQ;
    for (int k0 = 0; k0 < SEQ; k0 += 32){
        #pragma unroll
        for (int p = 0; p < 4; p++){
            int r = lr + p*32;
            *(float4*)&As[r][lc] = *(const float4*)(Abase + (size_t)(bm+r)*SEQ + k0 + lc);
        }
        #pragma unroll
        for (int i = 0; i < 4; i++){
            float4 v = *(const float4*)(g_owf + ((size_t)(k0+bkk)*BATCH + b)*HID + bn + bh0 + 4*i);
            Bs[bh0+4*i+0][bkk] = v.x;
            Bs[bh0+4*i+1][bkk] = v.y;
            Bs[bh0+4*i+2][bkk] = v.z;
            Bs[bh0+4*i+3][bkk] = v.w;
        }
        __syncthreads();
        #pragma unroll
        for (int kk = 0; kk < 32; kk += 8){
            unsigned af[4][4];
            #pragma unroll
            for (int mi=0;mi<4;mi++){
                int row = wr*64 + mi*16 + gr;
                af[mi][0] = __float_as_uint(As[row  ][kk+gc  ]);
                af[mi][1] = __float_as_uint(As[row+8][kk+gc  ]);
                af[mi][2] = __float_as_uint(As[row  ][kk+gc+4]);
                af[mi][3] = __float_as_uint(As[row+8][kk+gc+4]);
            }
            unsigned bf[4][2];
            #pragma unroll
            for (int ni=0;ni<4;ni++){
                int row = wc*32 + ni*8 + gr;
                bf[ni][0] = __float_as_uint(Bs[row][kk+gc  ]);
                bf[ni][1] = __float_as_uint(Bs[row][kk+gc+4]);
            }
            #pragma unroll
            for (int mi=0;mi<4;mi++)
                #pragma unroll
                for (int ni=0;ni<4;ni++)
                    mma_tf32(acc[mi][ni], af[mi][0],af[mi][1],af[mi][2],af[mi][3],
                             bf[ni][0], bf[ni][1]);
        }
        __syncthreads();
    }
    #pragma unroll
    for (int mi=0;mi<4;mi++){
        int m0 = bm + wr*64 + mi*16 + gr;
        int m1 = m0 + 8;
        #pragma unroll
        for (int ni=0;ni<4;ni++){
            int n0 = bn + wc*32 + ni*8 + gc*2;
            unsigned p0 = bf16x2(acc[mi][ni][1], acc[mi][ni][0]);
            unsigned p1 = bf16x2(acc[mi][ni][3], acc[mi][ni][2]);
            *(unsigned*)(g_ctxh + ((size_t)m0*BATCH + b)*HID + n0) = p0;
            *(unsigned*)(g_ctxh + ((size_t)m1*BATCH + b)*HID + n0) = p1;
        }
    }
}

// -------- kernel 5b: pipelined bf16 MMA (m16n8k16): y = ctx @ W^T + ub -------
__global__ __launch_bounds__(256) void k_final3(float* __restrict__ out){
    __shared__ __nv_bfloat16 As[2][128][40];
    __shared__ __nv_bfloat16 Bs[2][128][40];
    const int tid = threadIdx.x;
    const int lane = tid & 31, wid = tid >> 5;
    const int wr = wid >> 2, wc = wid & 3;
    const int bm = blockIdx.x * 128, bn = blockIdx.y * 128;
    const int gr = lane >> 2, gc = lane & 3;
    const int lrow = tid >> 2;          // 0..63
    const int lchk = tid & 3;           // 16B chunk (8 bf16)
    const unsigned sA = smem_u32(&As[0][0][0]);
    const unsigned sB = smem_u32(&Bs[0][0][0]);
    float acc[4][4][4];
    #pragma unroll
    for (int mi=0;mi<4;mi++)
        #pragma unroll
        for (int ni=0;ni<4;ni++)
            #pragma unroll
            for (int rr=0;rr<4;rr++) acc[mi][ni][rr] = 0.f;

    #pragma unroll
    for (int p=0;p<2;p++){
        int r = lrow + p*64;
        unsigned doff = (unsigned)(r*80 + lchk*16);
        cp16(sA + doff, g_ctxh + (size_t)(bm+r)*HID + lchk*8);
        cp16(sB + doff, g_Whalf + (size_t)(bn+r)*HID + lchk*8);
    }
    asm volatile("cp.async.commit_group;");

    #pragma unroll 1
    for (int kt = 0; kt < 8; kt++){
        const int st = kt & 1;
        if (kt < 7){
            const int ns = st ^ 1;
            const int k1 = (kt+1)*32;
            #pragma unroll
            for (int p=0;p<2;p++){
                int r = lrow + p*64;
                unsigned doff = (unsigned)(ns*10240 + r*80 + lchk*16);
                cp16(sA + doff, g_ctxh + (size_t)(bm+r)*HID + k1 + lchk*8);
                cp16(sB + doff, g_Whalf + (size_t)(bn+r)*HID + k1 + lchk*8);
            }
            asm volatile("cp.async.commit_group;");
            asm volatile("cp.async.wait_group 1;");
        } else {
            asm volatile("cp.async.wait_group 0;");
        }
        __syncthreads();
        #pragma unroll
        for (int kk = 0; kk < 32; kk += 16){
            unsigned af[4][4];
            #pragma unroll
            for (int mi=0;mi<4;mi++){
                int row = wr*64 + mi*16 + gr;
                af[mi][0] = *(const unsigned*)&As[st][row  ][kk+gc*2  ];
                af[mi][1] = *(const unsigned*)&As[st][row+8][kk+gc*2  ];
                af[mi][2] = *(const unsigned*)&As[st][row  ][kk+gc*2+8];
                af[mi][3] = *(const unsigned*)&As[st][row+8][kk+gc*2+8];
            }
            unsigned bf[4][2];
            #pragma unroll
            for (int ni=0;ni<4;ni++){
                int row = wc*32 + ni*8 + gr;
                bf[ni][0] = *(const unsigned*)&Bs[st][row][kk+gc*2  ];
                bf[ni][1] = *(const unsigned*)&Bs[st][row][kk+gc*2+8];
            }
            #pragma unroll
            for (int mi=0;mi<4;mi++)
                #pragma unroll
                for (int ni=0;ni<4;ni++)
                    mma_bf16(acc[mi][ni], af[mi][0],af[mi][1],af[mi][2],af[mi][3],
                             bf[ni][0], bf[ni][1]);
        }
        __syncthreads();
    }
    #pragma unroll
    for (int mi=0;mi<4;mi++){
        int m0 = bm + wr*64 + mi*16 + gr;
        int m1 = m0 + 8;
        int b0i = m0 & 15, b1i = m1 & 15;
        #pragma unroll
        for (int ni=0;ni<4;ni++){
            int n0 = bn + wc*32 + ni*8 + gc*2;
            if (n0 < VOC){
                out[(size_t)m0*VOC + n0] = acc[mi][ni][0] + g_ub[(size_t)b0i*VOC + n0];
                out[(size_t)m1*VOC + n0] = acc[mi][ni][2] + g_ub[(size_t)b1i*VOC + n0];
            }
            if (n0+1 < VOC){
                out[(size_t)m0*VOC + n0+1] = acc[mi][ni][1] + g_ub[(size_t)b0i*VOC + n0+1];
                out[(size_t)m1*VOC + n0+1] = acc[mi][ni][3] + g_ub[(size_t)b1i*VOC + n0+1];
            }
        }
    }
}

// ------------------- tail: h_out [2,B,H] after y ----------------------------
__global__ void k_tail(float* __restrict__ out){
    int tid = blockIdx.x*256 + threadIdx.x;  // 8192
    out[(size_t)SB*VOC + tid] = g_hfin[tid];
}

extern "C" void kernel_launch(void* const* d_in, const int* in_sizes, int n_in,
                              void* d_out, int out_size){
    const int*   x    = (const int*)  d_in[0];
    const float* t    = (const float*)d_in[1];
    const float* s    = (const float*)d_in[2];
    const float* h0   = (const float*)d_in[5];
    const int*   au   = (const int*)  d_in[6];
    const float* enc  = (const float*)d_in[7];
    const float* uemb = (const float*)d_in[8];
    const float* Wihf = (const float*)d_in[9];
    const float* Whhf = (const float*)d_in[10];
    const float* bf   = (const float*)d_in[11];
    const float* Wihb = (const float*)d_in[12];
    const float* Whhb = (const float*)d_in[13];
    const float* bb   = (const float*)d_in[14];
    const float* fcW  = (const float*)d_in[15];
    const float* fcb  = (const float*)d_in[16];
    float* out = (float*)d_out;

    k_xpre_mma  <<<dim3(64,2,2), 256>>>(x, enc, Wihf, bf, Wihb, bb);
    k_fused     <<<NB_ALL, 512>>>(Whhf, Whhb, h0, t, s, fcW, fcb, au, uemb);
    k_owf_mma   <<<dim3(4,2,BATCH), 256>>>();
    k_scores_mma<<<dim3(4,4,BATCH), 256>>>();   // ncu capture slot
    k_softmax   <<<BATCH*SEQ, 256>>>();
    k_ctx_mma   <<<dim3(4,2,BATCH), 256>>>();
    k_final3    <<<dim3(SB/128, VOCP/128), 256>>>(out);
    if (out_size > SB*VOC) k_tail<<<32, 256>>>(out);
}